// round 1
// baseline (speedup 1.0000x reference)
#include <cuda_runtime.h>
#include <cstdint>

// Problem dims (fixed by the dataset)
#define M_TOK 8192   // B*S = 4*2048
#define D_DIM 2048
#define H_DIM 8192
#define R_DIM 16

// Scratch: __device__ globals (allocation inside kernel_launch is forbidden)
__device__ float g_x2[(size_t)M_TOK * H_DIM];   // relu(y1), 256 MB
__device__ float g_t[(size_t)M_TOK * R_DIM];    // LoRA intermediate, reused for both layers

// ---------------------------------------------------------------------------
// T = X @ A   (A is [K,16]); block = 128 rows, 128 threads, 1 row/thread
// ---------------------------------------------------------------------------
__global__ __launch_bounds__(128) void lora_t_kernel(
    const float* __restrict__ X, const float* __restrict__ A,
    float* __restrict__ T, int K)
{
    __shared__ float Xs[128][33];      // +1 pad: conflict-free Xs[t][kk] reads
    __shared__ float As[32][R_DIM];

    const int m0 = blockIdx.x * 128;
    const int t  = threadIdx.x;

    float acc[R_DIM];
#pragma unroll
    for (int r = 0; r < R_DIM; r++) acc[r] = 0.f;

    for (int k0 = 0; k0 < K; k0 += 32) {
        // X tile 128x32 via float4 (1024 float4, 8/thread)
#pragma unroll
        for (int j = 0; j < 8; j++) {
            int idx = t + 128 * j;
            int row = idx >> 3;
            int col = (idx & 7) << 2;
            float4 v = *reinterpret_cast<const float4*>(
                &X[(size_t)(m0 + row) * K + k0 + col]);
            Xs[row][col]   = v.x; Xs[row][col+1] = v.y;
            Xs[row][col+2] = v.z; Xs[row][col+3] = v.w;
        }
        // A tile 32x16 (512 elems, 4/thread)
#pragma unroll
        for (int j = 0; j < 4; j++) {
            int idx = t + 128 * j;
            int row = idx >> 4, col = idx & 15;
            As[row][col] = A[(size_t)(k0 + row) * R_DIM + col];
        }
        __syncthreads();
#pragma unroll
        for (int kk = 0; kk < 32; kk++) {
            float x = Xs[t][kk];
#pragma unroll
            for (int r = 0; r < R_DIM; r++) acc[r] += x * As[kk][r];
        }
        __syncthreads();
    }
#pragma unroll
    for (int r = 0; r < R_DIM; r++)
        T[(size_t)(m0 + t) * R_DIM + r] = acc[r];
}

// ---------------------------------------------------------------------------
// Y[M,N] = X[M,K] @ dequant(Wq[N,K], Wsc[N,K/64])^T + bias + T@LB  (opt. relu)
// 128x128x16 tile, 256 threads, 8x8 micro-tile per thread.
// ---------------------------------------------------------------------------
template<bool RELU>
__global__ __launch_bounds__(256, 2) void gemm_dq_lora(
    const float* __restrict__ X,     // [M, K]
    const int*   __restrict__ Wq,    // [N, K] int codes in [0,16)
    const float* __restrict__ Wsc,   // [N, K/64]
    const float* __restrict__ bias,  // [N]
    const float* __restrict__ T,     // [M, 16]
    const float* __restrict__ LB,    // [16, N]
    float* __restrict__ Y,           // [M, N]
    int K, int N)
{
    constexpr int BM = 128, BN = 128, BK = 16;
    __shared__ float As[BK][BM + 4];   // +4 keeps 16B alignment, breaks store conflicts
    __shared__ float Bs[BK][BN];
    __shared__ float Ts[BM][R_DIM];
    __shared__ float Ls[R_DIM][BN];

    const int t   = threadIdx.x;
    const int tx  = t & 15, ty = t >> 4;
    const int bn0 = blockIdx.x * BN;
    const int bm0 = blockIdx.y * BM;
    const int KB  = K >> 6;            // scale blocks along K

    float acc[8][8];
#pragma unroll
    for (int i = 0; i < 8; i++)
#pragma unroll
        for (int j = 0; j < 8; j++) acc[i][j] = 0.f;

    for (int k0 = 0; k0 < K; k0 += BK) {
        // --- A tile: 128 rows x 16 k (512 float4, 2/thread), stored transposed
#pragma unroll
        for (int j = 0; j < 2; j++) {
            int idx = t + 256 * j;
            int row = idx >> 2;
            int c4  = (idx & 3) << 2;
            float4 v = *reinterpret_cast<const float4*>(
                &X[(size_t)(bm0 + row) * K + k0 + c4]);
            As[c4][row]   = v.x; As[c4+1][row] = v.y;
            As[c4+2][row] = v.z; As[c4+3][row] = v.w;
        }
        // --- B tile: 128 n-rows x 16 k, int4 load + fused dequant
#pragma unroll
        for (int j = 0; j < 2; j++) {
            int idx = t + 256 * j;
            int row = idx >> 2;
            int c4  = (idx & 3) << 2;
            const int4 q = *reinterpret_cast<const int4*>(
                &Wq[(size_t)(bn0 + row) * K + k0 + c4]);
            float s = Wsc[(size_t)(bn0 + row) * KB + (k0 >> 6)];
            Bs[c4][row]   = ((float)q.x - 7.5f) * s;
            Bs[c4+1][row] = ((float)q.y - 7.5f) * s;
            Bs[c4+2][row] = ((float)q.z - 7.5f) * s;
            Bs[c4+3][row] = ((float)q.w - 7.5f) * s;
        }
        __syncthreads();

#pragma unroll
        for (int kk = 0; kk < BK; kk++) {
            float a[8], b[8];
            *reinterpret_cast<float4*>(&a[0]) =
                *reinterpret_cast<const float4*>(&As[kk][ty * 8]);
            *reinterpret_cast<float4*>(&a[4]) =
                *reinterpret_cast<const float4*>(&As[kk][ty * 8 + 4]);
            *reinterpret_cast<float4*>(&b[0]) =
                *reinterpret_cast<const float4*>(&Bs[kk][tx * 8]);
            *reinterpret_cast<float4*>(&b[4]) =
                *reinterpret_cast<const float4*>(&Bs[kk][tx * 8 + 4]);
#pragma unroll
            for (int i = 0; i < 8; i++)
#pragma unroll
                for (int j = 0; j < 8; j++)
                    acc[i][j] += a[i] * b[j];
        }
        __syncthreads();
    }

    // --- epilogue: bias + LoRA (T[m,:] . LB[:,n]) [+ relu]
#pragma unroll
    for (int j = 0; j < 8; j++) {           // Ts: 128x16
        int idx = t + 256 * j;
        int row = idx >> 4, col = idx & 15;
        Ts[row][col] = T[(size_t)(bm0 + row) * R_DIM + col];
    }
#pragma unroll
    for (int j = 0; j < 8; j++) {           // Ls: 16x128
        int idx = t + 256 * j;
        int row = idx >> 7, col = idx & 127;
        Ls[row][col] = LB[(size_t)row * N + bn0 + col];
    }
    __syncthreads();

    float bv[8];
#pragma unroll
    for (int j = 0; j < 8; j++) bv[j] = bias[bn0 + tx * 8 + j];

#pragma unroll
    for (int i = 0; i < 8; i++) {
        const int m = ty * 8 + i;
        float v[8];
#pragma unroll
        for (int j = 0; j < 8; j++) v[j] = acc[i][j] + bv[j];
#pragma unroll
        for (int r = 0; r < R_DIM; r++) {
            float tm = Ts[m][r];
#pragma unroll
            for (int j = 0; j < 8; j++) v[j] += tm * Ls[r][tx * 8 + j];
        }
        if (RELU) {
#pragma unroll
            for (int j = 0; j < 8; j++) v[j] = fmaxf(v[j], 0.f);
        }
        float* yp = &Y[(size_t)(bm0 + m) * N + bn0 + tx * 8];
        *reinterpret_cast<float4*>(yp)     = make_float4(v[0], v[1], v[2], v[3]);
        *reinterpret_cast<float4*>(yp + 4) = make_float4(v[4], v[5], v[6], v[7]);
    }
}

// ---------------------------------------------------------------------------
extern "C" void kernel_launch(void* const* d_in, const int* in_sizes, int n_in,
                              void* d_out, int out_size)
{
    const float* x1        = (const float*)d_in[0];
    const int*   w_up_q    = (const int*)  d_in[1];
    const float* w_up_sc   = (const float*)d_in[2];
    const float* b_up      = (const float*)d_in[3];
    const float* w_up_la   = (const float*)d_in[4];
    const float* w_up_lb   = (const float*)d_in[5];
    const int*   w_dn_q    = (const int*)  d_in[6];
    const float* w_dn_sc   = (const float*)d_in[7];
    const float* b_dn      = (const float*)d_in[8];
    const float* w_dn_la   = (const float*)d_in[9];
    const float* w_dn_lb   = (const float*)d_in[10];
    float*       out       = (float*)d_out;

    float* x2; float* tt;
    cudaGetSymbolAddress((void**)&x2, g_x2);
    cudaGetSymbolAddress((void**)&tt, g_t);

    // T1 = x1 @ w_up_lora_a
    lora_t_kernel<<<M_TOK / 128, 128>>>(x1, w_up_la, tt, D_DIM);
    // x2 = relu(x1 @ dequant(w_up)^T + b_up + T1 @ w_up_lora_b)
    gemm_dq_lora<true><<<dim3(H_DIM / 128, M_TOK / 128), 256>>>(
        x1, w_up_q, w_up_sc, b_up, tt, w_up_lb, x2, D_DIM, H_DIM);
    // T2 = x2 @ w_down_lora_a
    lora_t_kernel<<<M_TOK / 128, 128>>>(x2, w_dn_la, tt, H_DIM);
    // out = x2 @ dequant(w_down)^T + b_down + T2 @ w_down_lora_b
    gemm_dq_lora<false><<<dim3(D_DIM / 128, M_TOK / 128), 256>>>(
        x2, w_dn_q, w_dn_sc, b_dn, tt, w_dn_lb, out, H_DIM, D_DIM);
}

// round 3
// speedup vs baseline: 2.1634x; 2.1634x over previous
#include <cuda_runtime.h>
#include <cstdint>

#define M_TOK 8192
#define D_DIM 2048
#define H_DIM 8192

// device-global scratch (no allocation allowed in kernel_launch)
__device__ float g_x2[(size_t)M_TOK * H_DIM];        // relu(y1)
__device__ float g_tp[4 * (size_t)M_TOK * 16];       // k-split partials of T = X @ lora_a
__device__ float g_ts[(size_t)M_TOK * 16];           // summed T

// ---------------------------------------------------------------------------
__device__ __forceinline__ uint32_t f2tf32(float x) {
    uint32_t u;
    asm("cvt.rna.tf32.f32 %0, %1;" : "=r"(u) : "f"(x));
    return u;
}
__device__ __forceinline__ void mma1688(float* d, uint32_t a0, uint32_t a1,
                                        uint32_t a2, uint32_t a3,
                                        uint32_t b0, uint32_t b1) {
    asm volatile("mma.sync.aligned.m16n8k8.row.col.f32.tf32.tf32.f32 "
                 "{%0,%1,%2,%3}, {%4,%5,%6,%7}, {%8,%9}, {%0,%1,%2,%3};"
                 : "+f"(d[0]), "+f"(d[1]), "+f"(d[2]), "+f"(d[3])
                 : "r"(a0), "r"(a1), "r"(a2), "r"(a3), "r"(b0), "r"(b1));
}

// ---------------------------------------------------------------------------
// LoRA stage 1: Tp[q][m][r] = sum_{k in quarter q} X[m,k] * A[k,r]
// ---------------------------------------------------------------------------
__global__ __launch_bounds__(256) void lora4(const float* __restrict__ X,
                                             const float* __restrict__ A,
                                             float* __restrict__ Tp, int K)
{
    __shared__ float As[4][32][16];
    const int t = threadIdx.x;
    const int q = t >> 6;
    const int row = t & 63;
    const size_t m = (size_t)blockIdx.x * 64 + row;
    const int KQ = K >> 2;
    const int kb = q * KQ;

    float acc[16];
#pragma unroll
    for (int r = 0; r < 16; r++) acc[r] = 0.f;

    for (int kt = 0; kt < KQ; kt += 32) {
#pragma unroll
        for (int i = 0; i < 8; i++) {
            int j = t + (i << 8);
            int qq = j >> 9, kk = (j >> 4) & 31, r = j & 15;
            As[qq][kk][r] = A[(size_t)(qq * KQ + kt + kk) * 16 + r];
        }
        __syncthreads();
        float xr[32];
#pragma unroll
        for (int i = 0; i < 8; i++)
            *(float4*)&xr[i * 4] = *(const float4*)(X + m * K + kb + kt + i * 4);
#pragma unroll
        for (int kk = 0; kk < 32; kk++)
#pragma unroll
            for (int r = 0; r < 16; r++)
                acc[r] = fmaf(xr[kk], As[q][kk][r], acc[r]);
        __syncthreads();
    }
    float* o = Tp + ((size_t)q * M_TOK + m) * 16;
#pragma unroll
    for (int r = 0; r < 16; r += 4)
        *(float4*)(o + r) = make_float4(acc[r], acc[r + 1], acc[r + 2], acc[r + 3]);
}

// LoRA stage 2: Ts = sum of 4 partials
__global__ __launch_bounds__(256) void lora_sum(const float* __restrict__ Tp,
                                                float* __restrict__ Ts)
{
    int i = blockIdx.x * 256 + threadIdx.x;          // float4 index, < 32768
    const float4* p = (const float4*)Tp;
    float4 a = p[i], b = p[i + 32768], c = p[i + 65536], d = p[i + 98304];
    ((float4*)Ts)[i] = make_float4(a.x + b.x + c.x + d.x, a.y + b.y + c.y + d.y,
                                   a.z + b.z + c.z + d.z, a.w + b.w + c.w + d.w);
}

// ---------------------------------------------------------------------------
// tf32 mma.sync GEMM:  Y[M,NT] = X[M,K] @ dequant(Wq[NT,K])^T + bias + Ts@LB [relu]
// CTA 128x256, BK=16, 512 threads (4x4 warps of 32x64), 3-stage smem ring.
// LoRA folded in as one extra k-tile (R=16 == BK).
// ---------------------------------------------------------------------------
template<bool RELU, int KTILES, int NT, int GROUP>
__global__ __launch_bounds__(512, 1) void gemm_mma(
    const float* __restrict__ X, const int* __restrict__ Wq,
    const float* __restrict__ Wsc, const float* __restrict__ bias,
    const float* __restrict__ Ts, const float* __restrict__ LB,
    float* __restrict__ Y)
{
    constexpr int K   = KTILES * 16;
    constexpr int KB  = K / 64;
    constexpr int NTILES = NT / 256;
    constexpr int TOT = KTILES + 1;
    constexpr int ASZ = 128 * 16 * 4;   // 8 KB
    constexpr int BSZ = 256 * 16 * 4;   // 16 KB
    constexpr int STG = ASZ + BSZ;      // 24 KB

    extern __shared__ __align__(16) char smem[];
    float* sbias = (float*)(smem + 3 * STG);

    const int tid  = threadIdx.x;
    const int lane = tid & 31;
    const int wid  = tid >> 5;
    const int wm = wid & 3, wn = wid >> 2;         // 4x4 warp grid
    const int lr = lane >> 2, lc = lane & 3;
    const uint32_t xoff = (uint32_t)((lc ^ (lr & 3)) << 4);   // swizzled quad byte-offset

    // grouped raster (m fastest within group) for L2 reuse
    constexpr int NPG = GROUP * NTILES;
    const int pid = blockIdx.x;
    const int grp = pid / NPG, rem = pid % NPG;
    const int bm0 = (grp * GROUP + rem % GROUP) * 128;
    const int bn0 = (rem / GROUP) * 256;

    if (tid < 256) sbias[tid] = bias[bn0 + tid];

    const int r  = tid >> 2;         // 0..127 (loader row)
    const int j4 = tid & 3;          // quad index along k

    float4 ra; uint4 rb0, rb1; float s0 = 0.f, s1 = 0.f;

    // ---- loader: fetch tile `it` into regs ----
    auto LOAD = [&](int it) {
        if (it < KTILES) {
            const int k0 = it * 16;
            ra  = *(const float4*)(X  + (size_t)(bm0 + r) * K + k0 + j4 * 4);
            rb0 = *(const uint4*) (Wq + (size_t)(bn0 + r) * K + k0 + j4 * 4);
            rb1 = *(const uint4*) (Wq + (size_t)(bn0 + r + 128) * K + k0 + j4 * 4);
            s0 = Wsc[(size_t)(bn0 + r) * KB + (it >> 2)];
            s1 = Wsc[(size_t)(bn0 + r + 128) * KB + (it >> 2)];
        } else {
            ra = *(const float4*)(Ts + (size_t)(bm0 + r) * 16 + j4 * 4);
            float b[8];
#pragma unroll
            for (int e = 0; e < 4; e++) {
                b[e]     = LB[(size_t)(j4 * 4 + e) * NT + bn0 + r];
                b[4 + e] = LB[(size_t)(j4 * 4 + e) * NT + bn0 + r + 128];
            }
            rb0 = make_uint4(__float_as_uint(b[0]), __float_as_uint(b[1]),
                             __float_as_uint(b[2]), __float_as_uint(b[3]));
            rb1 = make_uint4(__float_as_uint(b[4]), __float_as_uint(b[5]),
                             __float_as_uint(b[6]), __float_as_uint(b[7]));
        }
    };

    // ---- store staged regs (tile `it`) into smem stage `stg` ----
    auto STS = [&](int it, int stg) {
        char* sA = smem + stg * STG;
        char* sB = sA + ASZ;
        const bool mn = (it < KTILES);
        const float av[4] = {ra.x, ra.y, ra.z, ra.w};
        const uint32_t q0[4] = {rb0.x, rb0.y, rb0.z, rb0.w};
        const uint32_t q1[4] = {rb1.x, rb1.y, rb1.z, rb1.w};
#pragma unroll
        for (int e = 0; e < 4; e++) {
            const uint32_t sw = (uint32_t)(((e ^ (r & 3)) << 2) + j4) * 4;
            *(uint32_t*)(sA + (uint32_t)r * 64 + sw) = f2tf32(av[e]);
            float v0 = mn ? ((float)(int)q0[e] - 7.5f) * s0 : __uint_as_float(q0[e]);
            float v1 = mn ? ((float)(int)q1[e] - 7.5f) * s1 : __uint_as_float(q1[e]);
            *(uint32_t*)(sB + (uint32_t)r * 64 + sw)          = f2tf32(v0);
            *(uint32_t*)(sB + (uint32_t)(r + 128) * 64 + sw)  = f2tf32(v1);
        }
    };

    float acc[2][8][4];
#pragma unroll
    for (int i = 0; i < 2; i++)
#pragma unroll
        for (int j = 0; j < 8; j++)
#pragma unroll
            for (int k = 0; k < 4; k++) acc[i][j][k] = 0.f;

    LOAD(0); STS(0, 0); LOAD(1);
    __syncthreads();

    int stg = 0;
    for (int it = 0; it < TOT; ++it) {
        const int nstg = (stg == 2) ? 0 : stg + 1;
        if (it + 1 < TOT) STS(it + 1, nstg);
        if (it + 2 < TOT) LOAD(it + 2);

        // ---- compute on stage `stg` ----
        const char* sA = smem + stg * STG;
        const char* sB = sA + ASZ;
        uint32_t a[2][2][4];
#pragma unroll
        for (int mt = 0; mt < 2; mt++) {
            const uint32_t row = (uint32_t)(32 * wm + 16 * mt + lr);
            *(uint4*)a[mt][0] = *(const uint4*)(sA + row * 64 + xoff);
            *(uint4*)a[mt][1] = *(const uint4*)(sA + (row + 8) * 64 + xoff);
        }
#pragma unroll
        for (int nt = 0; nt < 8; nt++) {
            const uint32_t n = (uint32_t)(64 * wn + 8 * nt + lr);
            uint32_t b[4];
            *(uint4*)b = *(const uint4*)(sB + n * 64 + xoff);
#pragma unroll
            for (int mt = 0; mt < 2; mt++) {
                mma1688(acc[mt][nt], a[mt][0][0], a[mt][1][0], a[mt][0][1], a[mt][1][1],
                        b[0], b[1]);
                mma1688(acc[mt][nt], a[mt][0][2], a[mt][1][2], a[mt][0][3], a[mt][1][3],
                        b[2], b[3]);
            }
        }
        stg = nstg;
        __syncthreads();
    }

    // ---- epilogue: bias (+relu); LoRA already accumulated via extra k-tile ----
#pragma unroll
    for (int mt = 0; mt < 2; mt++) {
        const int m = bm0 + 32 * wm + 16 * mt + lr;
#pragma unroll
        for (int nt = 0; nt < 8; nt++) {
            const int ncol = 64 * wn + 8 * nt + 2 * lc;
            const float b0 = sbias[ncol], b1 = sbias[ncol + 1];
            float v0 = acc[mt][nt][0] + b0, v1 = acc[mt][nt][1] + b1;
            float v2 = acc[mt][nt][2] + b0, v3 = acc[mt][nt][3] + b1;
            if (RELU) {
                v0 = fmaxf(v0, 0.f); v1 = fmaxf(v1, 0.f);
                v2 = fmaxf(v2, 0.f); v3 = fmaxf(v3, 0.f);
            }
            *(float2*)(Y + (size_t)m * NT + bn0 + ncol)       = make_float2(v0, v1);
            *(float2*)(Y + (size_t)(m + 8) * NT + bn0 + ncol) = make_float2(v2, v3);
        }
    }
}

// ---------------------------------------------------------------------------
extern "C" void kernel_launch(void* const* d_in, const int* in_sizes, int n_in,
                              void* d_out, int out_size)
{
    const float* x1      = (const float*)d_in[0];
    const int*   w_up_q  = (const int*)  d_in[1];
    const float* w_up_sc = (const float*)d_in[2];
    const float* b_up    = (const float*)d_in[3];
    const float* w_up_la = (const float*)d_in[4];
    const float* w_up_lb = (const float*)d_in[5];
    const int*   w_dn_q  = (const int*)  d_in[6];
    const float* w_dn_sc = (const float*)d_in[7];
    const float* b_dn    = (const float*)d_in[8];
    const float* w_dn_la = (const float*)d_in[9];
    const float* w_dn_lb = (const float*)d_in[10];
    float*       out     = (float*)d_out;

    float *x2, *tp, *ts;
    cudaGetSymbolAddress((void**)&x2, g_x2);
    cudaGetSymbolAddress((void**)&tp, g_tp);
    cudaGetSymbolAddress((void**)&ts, g_ts);

    constexpr int SMEM = 3 * (128 * 16 * 4 + 256 * 16 * 4) + 1024 + 16;
    cudaFuncSetAttribute(gemm_mma<true, 128, H_DIM, 16>,
                         cudaFuncAttributeMaxDynamicSharedMemorySize, SMEM);
    cudaFuncSetAttribute(gemm_mma<false, 512, D_DIM, 32>,
                         cudaFuncAttributeMaxDynamicSharedMemorySize, SMEM);

    // layer 1
    lora4<<<M_TOK / 64, 256>>>(x1, w_up_la, tp, D_DIM);
    lora_sum<<<128, 256>>>(tp, ts);
    gemm_mma<true, 128, H_DIM, 16><<<(M_TOK / 128) * (H_DIM / 256), 512, SMEM>>>(
        x1, w_up_q, w_up_sc, b_up, ts, w_up_lb, x2);
    // layer 2
    lora4<<<M_TOK / 64, 256>>>(x2, w_dn_la, tp, H_DIM);
    lora_sum<<<128, 256>>>(tp, ts);
    gemm_mma<false, 512, D_DIM, 32><<<(M_TOK / 128) * (D_DIM / 256), 512, SMEM>>>(
        x2, w_dn_q, w_dn_sc, b_dn, ts, w_dn_lb, out);
}

// round 4
// speedup vs baseline: 2.7806x; 1.2853x over previous
#include <cuda_runtime.h>
#include <cstdint>

#define M_TOK 8192
#define D_DIM 2048
#define H_DIM 8192

// device-global scratch (no allocation allowed in kernel_launch)
__device__ float g_x2[(size_t)M_TOK * H_DIM];        // relu(y1)
__device__ float g_tp[8 * (size_t)M_TOK * 16];       // k-split partials of T = X @ lora_a
__device__ float g_ts[(size_t)M_TOK * 16];           // summed T

// ---------------------------------------------------------------------------
__device__ __forceinline__ uint32_t f2tf32(float x) {
    uint32_t u;
    asm("cvt.rna.tf32.f32 %0, %1;" : "=r"(u) : "f"(x));
    return u;
}
__device__ __forceinline__ void mma1688(float* d, uint32_t a0, uint32_t a1,
                                        uint32_t a2, uint32_t a3,
                                        uint32_t b0, uint32_t b1) {
    asm volatile("mma.sync.aligned.m16n8k8.row.col.f32.tf32.tf32.f32 "
                 "{%0,%1,%2,%3}, {%4,%5,%6,%7}, {%8,%9}, {%0,%1,%2,%3};"
                 : "+f"(d[0]), "+f"(d[1]), "+f"(d[2]), "+f"(d[3])
                 : "r"(a0), "r"(a1), "r"(a2), "r"(a3), "r"(b0), "r"(b1));
}

// ---------------------------------------------------------------------------
// LoRA stage 1: Tp[split][m][r] = sum_{k in split chunk} X[m,k] * A[k,r]
// block 256 = 8 warps; warp = 4 rows x 32 lanes along k (coalesced X reads).
// grid = (M/32, SPLIT), chunk KC = K/SPLIT (multiple of 128).
// ---------------------------------------------------------------------------
__global__ __launch_bounds__(256) void lora_t(const float* __restrict__ X,
                                              const float* __restrict__ A,
                                              float* __restrict__ Tp,
                                              int K, int KC)
{
    __shared__ float As[128][17];
    const int tid = threadIdx.x, lane = tid & 31, w = tid >> 5;
    const int m0 = blockIdx.x * 32 + w * 4;
    const int k0 = blockIdx.y * KC;

    float acc[4][16];
#pragma unroll
    for (int rr = 0; rr < 4; rr++)
#pragma unroll
        for (int r = 0; r < 16; r++) acc[rr][r] = 0.f;

    for (int kt = 0; kt < KC; kt += 128) {
        __syncthreads();
#pragma unroll
        for (int i = 0; i < 2; i++) {          // A chunk 128x16 -> smem (pad 17)
            int c = tid + 256 * i;
            int row = c >> 2, q = (c & 3) * 4;
            float4 v = *(const float4*)(A + (size_t)(k0 + kt + row) * 16 + q);
            As[row][q] = v.x; As[row][q + 1] = v.y;
            As[row][q + 2] = v.z; As[row][q + 3] = v.w;
        }
        __syncthreads();
#pragma unroll
        for (int j = 0; j < 4; j++) {
            const int kl = lane + 32 * j;
            float x[4];
#pragma unroll
            for (int rr = 0; rr < 4; rr++)
                x[rr] = X[(size_t)(m0 + rr) * K + k0 + kt + kl];
#pragma unroll
            for (int r = 0; r < 16; r++) {
                const float a = As[kl][r];
#pragma unroll
                for (int rr = 0; rr < 4; rr++)
                    acc[rr][r] = fmaf(x[rr], a, acc[rr][r]);
            }
        }
    }

    // cross-lane reduce; lane r keeps the r-th column
    float keep[4];
#pragma unroll
    for (int r = 0; r < 16; r++) {
#pragma unroll
        for (int rr = 0; rr < 4; rr++) {
            float v = acc[rr][r];
#pragma unroll
            for (int s = 16; s; s >>= 1) v += __shfl_xor_sync(~0u, v, s);
            if (lane == r) keep[rr] = v;
        }
    }
    if (lane < 16) {
        float* o = Tp + (size_t)blockIdx.y * (M_TOK * 16);
#pragma unroll
        for (int rr = 0; rr < 4; rr++)
            o[(size_t)(m0 + rr) * 16 + lane] = keep[rr];
    }
}

// LoRA stage 2: Ts = sum of SPLIT partials
__global__ __launch_bounds__(256) void lora_sum(const float* __restrict__ Tp,
                                                float* __restrict__ Ts, int split)
{
    const int i = blockIdx.x * 256 + threadIdx.x;   // float4 index, < 32768
    const float4* p = (const float4*)Tp;
    float4 a = p[i];
    for (int s = 1; s < split; s++) {
        float4 b = p[i + (size_t)s * 32768];
        a.x += b.x; a.y += b.y; a.z += b.z; a.w += b.w;
    }
    ((float4*)Ts)[i] = a;
}

// ---------------------------------------------------------------------------
// tf32 mma.sync GEMM:  Y[M,NT] = X[M,K] @ dequant(Wq[NT,K])^T + bias + Ts@LB [relu]
// CTA 128x128, BK=16, 256 threads (4x2 warps of 32x64), 3-stage smem ring,
// 2 CTAs/SM. LoRA folded in as one extra k-tile (R=16 == BK).
// ---------------------------------------------------------------------------
template<bool RELU, int KTILES, int NT, int GROUP>
__global__ __launch_bounds__(256, 2) void gemm_mma(
    const float* __restrict__ X, const int* __restrict__ Wq,
    const float* __restrict__ Wsc, const float* __restrict__ bias,
    const float* __restrict__ Ts, const float* __restrict__ LB,
    float* __restrict__ Y)
{
    constexpr int K   = KTILES * 16;
    constexpr int KB  = K / 64;
    constexpr int NTILES = NT / 128;
    constexpr int TOT = KTILES + 1;
    constexpr int ASZ = 128 * 16 * 4;   // 8 KB
    constexpr int BSZ = 128 * 16 * 4;   // 8 KB
    constexpr int STG = ASZ + BSZ;      // 16 KB

    extern __shared__ __align__(16) char smem[];
    float* sbias = (float*)(smem + 3 * STG);

    const int tid  = threadIdx.x;
    const int lane = tid & 31;
    const int wid  = tid >> 5;
    const int wm = wid & 3, wn = wid >> 2;          // 4(m) x 2(n) warp grid
    const int lr = lane >> 2, lc = lane & 3;
    const uint32_t xoff = (uint32_t)((lc ^ (lr & 3)) << 4);

    // grouped raster (m fastest within group) for L2 reuse
    constexpr int NPG = GROUP * NTILES;
    const int pid = blockIdx.x;
    const int grp = pid / NPG, rem = pid % NPG;
    const int bm0 = (grp * GROUP + rem % GROUP) * 128;
    const int bn0 = (rem / GROUP) * 128;

    if (tid < 128) sbias[tid] = bias[bn0 + tid];

    const int r  = tid >> 2;        // 0..63 (plus +64 on second iter)
    const int j4 = tid & 3;

    float4 ra[2]; uint4 rb[2]; float s[2];

    auto LOAD = [&](int it) {
        if (it < KTILES) {
            const int k0 = it * 16;
#pragma unroll
            for (int j = 0; j < 2; j++) {
                const int row = r + 64 * j;
                ra[j] = *(const float4*)(X  + (size_t)(bm0 + row) * K + k0 + j4 * 4);
                rb[j] = *(const uint4*) (Wq + (size_t)(bn0 + row) * K + k0 + j4 * 4);
                s[j]  = Wsc[(size_t)(bn0 + row) * KB + (it >> 2)];
            }
        } else {
#pragma unroll
            for (int j = 0; j < 2; j++) {
                const int row = r + 64 * j;
                ra[j] = *(const float4*)(Ts + (size_t)(bm0 + row) * 16 + j4 * 4);
                float b[4];
#pragma unroll
                for (int e = 0; e < 4; e++)
                    b[e] = LB[(size_t)(j4 * 4 + e) * NT + bn0 + row];
                rb[j] = make_uint4(__float_as_uint(b[0]), __float_as_uint(b[1]),
                                   __float_as_uint(b[2]), __float_as_uint(b[3]));
            }
        }
    };

    auto STS = [&](int it, int stg) {
        char* sA = smem + stg * STG;
        char* sB = sA + ASZ;
        const bool mn = (it < KTILES);
#pragma unroll
        for (int j = 0; j < 2; j++) {
            const int row = r + 64 * j;
            const float av[4] = {ra[j].x, ra[j].y, ra[j].z, ra[j].w};
            const uint32_t qv[4] = {rb[j].x, rb[j].y, rb[j].z, rb[j].w};
#pragma unroll
            for (int e = 0; e < 4; e++) {
                const uint32_t sw = (uint32_t)(((e ^ (row & 3)) << 2) + j4) * 4;
                *(uint32_t*)(sA + (uint32_t)row * 64 + sw) = f2tf32(av[e]);
                float v = mn ? ((float)(int)qv[e] - 7.5f) * s[j]
                             : __uint_as_float(qv[e]);
                *(uint32_t*)(sB + (uint32_t)row * 64 + sw) = f2tf32(v);
            }
        }
    };

    float acc[2][8][4];
#pragma unroll
    for (int i = 0; i < 2; i++)
#pragma unroll
        for (int j = 0; j < 8; j++)
#pragma unroll
            for (int k = 0; k < 4; k++) acc[i][j][k] = 0.f;

    LOAD(0); STS(0, 0); LOAD(1);
    __syncthreads();

    int stg = 0;
    for (int it = 0; it < TOT; ++it) {
        const int nstg = (stg == 2) ? 0 : stg + 1;
        if (it + 1 < TOT) STS(it + 1, nstg);
        if (it + 2 < TOT) LOAD(it + 2);

        const char* sA = smem + stg * STG;
        const char* sB = sA + ASZ;
        uint32_t a[2][2][4];
#pragma unroll
        for (int mt = 0; mt < 2; mt++) {
            const uint32_t row = (uint32_t)(32 * wm + 16 * mt + lr);
            *(uint4*)a[mt][0] = *(const uint4*)(sA + row * 64 + xoff);
            *(uint4*)a[mt][1] = *(const uint4*)(sA + (row + 8) * 64 + xoff);
        }
#pragma unroll
        for (int nt = 0; nt < 8; nt++) {
            const uint32_t n = (uint32_t)(64 * wn + 8 * nt + lr);
            uint32_t b[4];
            *(uint4*)b = *(const uint4*)(sB + n * 64 + xoff);
#pragma unroll
            for (int mt = 0; mt < 2; mt++) {
                mma1688(acc[mt][nt], a[mt][0][0], a[mt][1][0], a[mt][0][1], a[mt][1][1],
                        b[0], b[1]);
                mma1688(acc[mt][nt], a[mt][0][2], a[mt][1][2], a[mt][0][3], a[mt][1][3],
                        b[2], b[3]);
            }
        }
        stg = nstg;
        __syncthreads();
    }

    // epilogue: bias (+relu); LoRA already in the accumulators
#pragma unroll
    for (int mt = 0; mt < 2; mt++) {
        const int m = bm0 + 32 * wm + 16 * mt + lr;
#pragma unroll
        for (int nt = 0; nt < 8; nt++) {
            const int ncol = 64 * wn + 8 * nt + 2 * lc;
            const float b0 = sbias[ncol], b1 = sbias[ncol + 1];
            float v0 = acc[mt][nt][0] + b0, v1 = acc[mt][nt][1] + b1;
            float v2 = acc[mt][nt][2] + b0, v3 = acc[mt][nt][3] + b1;
            if (RELU) {
                v0 = fmaxf(v0, 0.f); v1 = fmaxf(v1, 0.f);
                v2 = fmaxf(v2, 0.f); v3 = fmaxf(v3, 0.f);
            }
            *(float2*)(Y + (size_t)m * NT + bn0 + ncol)       = make_float2(v0, v1);
            *(float2*)(Y + (size_t)(m + 8) * NT + bn0 + ncol) = make_float2(v2, v3);
        }
    }
}

// ---------------------------------------------------------------------------
extern "C" void kernel_launch(void* const* d_in, const int* in_sizes, int n_in,
                              void* d_out, int out_size)
{
    const float* x1      = (const float*)d_in[0];
    const int*   w_up_q  = (const int*)  d_in[1];
    const float* w_up_sc = (const float*)d_in[2];
    const float* b_up    = (const float*)d_in[3];
    const float* w_up_la = (const float*)d_in[4];
    const float* w_up_lb = (const float*)d_in[5];
    const int*   w_dn_q  = (const int*)  d_in[6];
    const float* w_dn_sc = (const float*)d_in[7];
    const float* b_dn    = (const float*)d_in[8];
    const float* w_dn_la = (const float*)d_in[9];
    const float* w_dn_lb = (const float*)d_in[10];
    float*       out     = (float*)d_out;

    float *x2, *tp, *ts;
    cudaGetSymbolAddress((void**)&x2, g_x2);
    cudaGetSymbolAddress((void**)&tp, g_tp);
    cudaGetSymbolAddress((void**)&ts, g_ts);

    constexpr int SMEM = 3 * (128 * 16 * 4 + 128 * 16 * 4) + 512;
    cudaFuncSetAttribute(gemm_mma<true, 128, H_DIM, 16>,
                         cudaFuncAttributeMaxDynamicSharedMemorySize, SMEM);
    cudaFuncSetAttribute(gemm_mma<false, 512, D_DIM, 32>,
                         cudaFuncAttributeMaxDynamicSharedMemorySize, SMEM);

    // layer 1: T1 = x1 @ lora_a (split-K 4), then fused GEMM
    lora_t<<<dim3(M_TOK / 32, 4), 256>>>(x1, w_up_la, tp, D_DIM, D_DIM / 4);
    lora_sum<<<128, 256>>>(tp, ts, 4);
    gemm_mma<true, 128, H_DIM, 16><<<(M_TOK / 128) * (H_DIM / 128), 256, SMEM>>>(
        x1, w_up_q, w_up_sc, b_up, ts, w_up_lb, x2);
    // layer 2
    lora_t<<<dim3(M_TOK / 32, 8), 256>>>(x2, w_dn_la, tp, H_DIM, H_DIM / 8);
    lora_sum<<<128, 256>>>(tp, ts, 8);
    gemm_mma<false, 512, D_DIM, 32><<<(M_TOK / 128) * (D_DIM / 128), 256, SMEM>>>(
        x2, w_dn_q, w_dn_sc, b_dn, ts, w_dn_lb, out);
}